// round 14
// baseline (speedup 1.0000x reference)
#include <cuda_runtime.h>

// LIF forward: X[B=128, T=32, N=8192] fp32 -> spikes fp32 (same shape).
// Per (b, n): mem = mem + (x_t - mem)/2 ; spike = mem > 1 ; mem = 0 on spike.
//
// FINAL — locked after 13 rounds of single-variable probes.
//
// The problem is a touch-once 256 MiB stream (128 MiB read + 128 MiB
// write, ~3 flops/elem). Nine mechanisms probed across 13 benches:
//   - scalar LDG/STG float4 (this kernel)          38-41 us
//   - 2-column per-thread MLP (63 regs)            40.1 us (occ loss)
//   - explicit 4-deep load batching                39.8 us (neutral)
//   - cp.async.bulk/TMA + mbarrier 8-stage ring    38.0 us (neutral)
//   - reg-capped single-wave residency (occ 74%)   38.2 us (neutral)
//   - streaming .cs loads/stores                   39.4 us (neutral)
//   - write-through .wt stores                     40.5 us (neutral)
//   - bitpacked read/write phase separation        42.6 / 90 us (regs/spill)
//   - TPB=128 granularity                          40.8 us (neutral)
// Every well-formed variant sits in one noise band = ~7.0 TB/s effective
// steady-state HBM throughput (88% of the 8 TB/s spec), the practical
// ceiling for an interleaved 50/50 R/W stream. Compute pipes idle
// (fma ~4%, issue ~15%, tensor 0%): pure memory roofline. Byte count and
// direction mix are fixed by the problem (fp32 out, zero reuse), so no
// kernel-side transformation can move the bound.
//
// Layout: 1 thread = 1 float4 column (4 consecutive n); walks t with
// stride N/4 -> every warp issues perfectly coalesced 128B transactions.
// Full T=32 unroll lets ptxas batch independent LDG.128s ahead of the
// serial 2-FMA-per-step recurrence chain. regs=39, occ ~63%.

static constexpr int B = 128;
static constexpr int T = 32;
static constexpr int N = 8192;
static constexpr int N4 = N / 4;          // float4 columns per plane
static constexpr int TOTAL4 = B * N4;     // 262144 float4 lanes
static constexpr int TPB = 256;

__device__ __forceinline__ float4 step4(float4& m, const float4 x) {
    // exact reference rounding: mem += (x - mem) * 0.5f
    m.x = m.x + (x.x - m.x) * 0.5f;
    m.y = m.y + (x.y - m.y) * 0.5f;
    m.z = m.z + (x.z - m.z) * 0.5f;
    m.w = m.w + (x.w - m.w) * 0.5f;
    float4 s;
    s.x = (m.x > 1.0f) ? 1.0f : 0.0f;
    s.y = (m.y > 1.0f) ? 1.0f : 0.0f;
    s.z = (m.z > 1.0f) ? 1.0f : 0.0f;
    s.w = (m.w > 1.0f) ? 1.0f : 0.0f;
    // hard reset to 0 where spiked
    if (s.x != 0.0f) m.x = 0.0f;
    if (s.y != 0.0f) m.y = 0.0f;
    if (s.z != 0.0f) m.z = 0.0f;
    if (s.w != 0.0f) m.w = 0.0f;
    return s;
}

__global__ __launch_bounds__(TPB) void lif_kernel(const float4* __restrict__ X,
                                                  float4* __restrict__ out) {
    int idx = blockIdx.x * TPB + threadIdx.x;  // 0 .. TOTAL4-1
    if (idx >= TOTAL4) return;

    int b = idx / N4;
    int n4 = idx - b * N4;

    const float4* xp = X + (size_t)b * T * N4 + n4;
    float4* op = out + (size_t)b * T * N4 + n4;

    float4 m = make_float4(0.f, 0.f, 0.f, 0.f);

#pragma unroll
    for (int t = 0; t < T; t++) {
        float4 x = xp[(size_t)t * N4];
        float4 s = step4(m, x);
        op[(size_t)t * N4] = s;
    }
}

extern "C" void kernel_launch(void* const* d_in, const int* in_sizes, int n_in,
                              void* d_out, int out_size) {
    const float4* X = (const float4*)d_in[0];
    float4* out = (float4*)d_out;
    lif_kernel<<<TOTAL4 / TPB, TPB>>>(X, out);
}

// round 15
// speedup vs baseline: 1.0102x; 1.0102x over previous
#include <cuda_runtime.h>

// LIF forward: X[B=128, T=32, N=8192] fp32 -> spikes fp32.
// R15: Blackwell 256-bit vector memory ops (ld/st.global.v8.f32, sm_100a+).
// One thread owns 8 consecutive n; each t-step is ONE 32B load and ONE 32B
// store -> a warp's access is a single 1024B contiguous burst. Halves LSU
// issue + L1tex wavefront count per byte vs float4, doubles per-thread
// bytes in flight. Everything else identical to the locked R1 recurrence.

static constexpr int B = 128;
static constexpr int T = 32;
static constexpr int N = 8192;
static constexpr int N8 = N / 8;          // 1024 v8 columns per plane
static constexpr int TOTAL8 = B * N8;     // 131072 v8 lanes
static constexpr int TPB = 256;

struct f8 { float v[8]; };

__device__ __forceinline__ f8 ldg256(const float* p) {
    f8 r;
    asm volatile("ld.global.v8.f32 {%0,%1,%2,%3,%4,%5,%6,%7}, [%8];"
                 : "=f"(r.v[0]), "=f"(r.v[1]), "=f"(r.v[2]), "=f"(r.v[3]),
                   "=f"(r.v[4]), "=f"(r.v[5]), "=f"(r.v[6]), "=f"(r.v[7])
                 : "l"(p));
    return r;
}

__device__ __forceinline__ void stg256(float* p, const f8& r) {
    asm volatile("st.global.v8.f32 [%0], {%1,%2,%3,%4,%5,%6,%7,%8};"
                 :: "l"(p),
                    "f"(r.v[0]), "f"(r.v[1]), "f"(r.v[2]), "f"(r.v[3]),
                    "f"(r.v[4]), "f"(r.v[5]), "f"(r.v[6]), "f"(r.v[7])
                 : "memory");
}

__global__ __launch_bounds__(TPB) void lif_kernel(const float* __restrict__ X,
                                                  float* __restrict__ out) {
    int idx = blockIdx.x * TPB + threadIdx.x;  // 0 .. TOTAL8-1
    if (idx >= TOTAL8) return;

    int b = idx / N8;
    int n8 = idx - b * N8;

    const float* xp = X + (size_t)b * T * N + (size_t)n8 * 8;
    float* op = out + (size_t)b * T * N + (size_t)n8 * 8;

    float m[8];
#pragma unroll
    for (int i = 0; i < 8; i++) m[i] = 0.0f;

#pragma unroll
    for (int t = 0; t < T; t++) {
        f8 x = ldg256(xp + (size_t)t * N);
        f8 s;
#pragma unroll
        for (int i = 0; i < 8; i++) {
            // exact reference rounding: mem += (x - mem) * 0.5f
            m[i] = m[i] + (x.v[i] - m[i]) * 0.5f;
            float sp = (m[i] > 1.0f) ? 1.0f : 0.0f;
            if (sp != 0.0f) m[i] = 0.0f;
            s.v[i] = sp;
        }
        stg256(op + (size_t)t * N, s);
    }
}

extern "C" void kernel_launch(void* const* d_in, const int* in_sizes, int n_in,
                              void* d_out, int out_size) {
    const float* X = (const float*)d_in[0];
    float* out = (float*)d_out;
    lif_kernel<<<TOTAL8 / TPB, TPB>>>(X, out);
}